// round 2
// baseline (speedup 1.0000x reference)
#include <cuda_runtime.h>
#include <cuda_bf16.h>
#include <cstdint>

// Problem constants
#define B_      16
#define N_      8192
#define C_      6
#define K_      512      // NUM_GROUP
#define GS_     32       // GROUP_SIZE
#define BIGF    10000000000.0f
#define FLTMAX  3.402823466e+38f

// Output layout (float32, concatenated): neighborhood | center | nn_idx
#define NEIGH_ELEMS   (B_*K_*GS_*C_)   // 1,572,864
#define CENTER_ELEMS  (B_*K_*C_)       // 49,152
#define NN_ELEMS      (B_*K_*GS_)      // 262,144
#define CENTER_OFF    (NEIGH_ELEMS)
#define NN_OFF        (NEIGH_ELEMS + CENTER_ELEMS)

// Scratch: FPS-selected representative indices
__device__ int g_rep[B_ * K_];

// ---------------------------------------------------------------------------
// Kernel 1: Farthest Point Sampling. One CTA per batch, 1024 threads,
// 8 points per thread held in registers (coords + running min-dist).
// Exact arithmetic association of the reference:
//   d = ((dx*dx + dy*dy) + dz*dz)  [no FMA: XLA elementwise+reduce],
//   dists = min(dists, d), argmax first-index.
// ---------------------------------------------------------------------------
__global__ __launch_bounds__(1024, 1)
void fps_kernel(const float* __restrict__ pc, int* __restrict__ rep)
{
    const int b = blockIdx.x;
    const int t = threadIdx.x;
    const float* base = pc + (size_t)b * N_ * C_;

    float x[8], y[8], z[8], dst[8];
#pragma unroll
    for (int i = 0; i < 8; i++) {
        int j = t + i * 1024;
        const float* p = base + (size_t)j * C_;
        x[i] = p[0]; y[i] = p[1]; z[i] = p[2];
        dst[i] = BIGF;
    }

    __shared__ float s_val[32];
    __shared__ int   s_idx[32];
    __shared__ float s_q[3];
    __shared__ int   s_cur;

    if (t == 0) {
        s_q[0] = base[0]; s_q[1] = base[1]; s_q[2] = base[2];
        s_cur = 0;
    }
    __syncthreads();

    int* repb = rep + b * K_;

    for (int k = 0; k < K_; k++) {
        const float qx = s_q[0], qy = s_q[1], qz = s_q[2];
        if (t == 0) repb[k] = s_cur;

        float bv = -1.0f;
        int   bi = 0;
#pragma unroll
        for (int i = 0; i < 8; i++) {
            float dx = __fsub_rn(x[i], qx);
            float dy = __fsub_rn(y[i], qy);
            float dz = __fsub_rn(z[i], qz);
            float dd = __fadd_rn(__fadd_rn(__fmul_rn(dx, dx), __fmul_rn(dy, dy)),
                                 __fmul_rn(dz, dz));
            float nd = fminf(dst[i], dd);
            dst[i] = nd;
            // strict > keeps earliest (lowest global index for this thread)
            if (nd > bv) { bv = nd; bi = t + i * 1024; }
        }

        // warp-level argmax, tie -> lowest index
#pragma unroll
        for (int off = 16; off > 0; off >>= 1) {
            float ov = __shfl_down_sync(0xffffffffu, bv, off);
            int   oi = __shfl_down_sync(0xffffffffu, bi, off);
            if (ov > bv || (ov == bv && oi < bi)) { bv = ov; bi = oi; }
        }
        if ((t & 31) == 0) { s_val[t >> 5] = bv; s_idx[t >> 5] = bi; }
        __syncthreads();

        if (t < 32) {
            bv = s_val[t]; bi = s_idx[t];
#pragma unroll
            for (int off = 16; off > 0; off >>= 1) {
                float ov = __shfl_down_sync(0xffffffffu, bv, off);
                int   oi = __shfl_down_sync(0xffffffffu, bi, off);
                if (ov > bv || (ov == bv && oi < bi)) { bv = ov; bi = oi; }
            }
            if (t == 0) s_cur = bi;
        }
        __syncthreads();

        const int cur = s_cur;
        if (t == (cur & 1023)) {
            int i = cur >> 10;
            s_q[0] = x[i]; s_q[1] = y[i]; s_q[2] = z[i];
        }
        __syncthreads();
    }
}

// ---------------------------------------------------------------------------
// Kernel 2: gather centers (all 6 channels) into the output.
// ---------------------------------------------------------------------------
__global__ void center_kernel(const float* __restrict__ pc,
                              const int* __restrict__ rep,
                              float* __restrict__ out)
{
    int i = blockIdx.x * blockDim.x + threadIdx.x;
    if (i >= CENTER_ELEMS) return;
    int c  = i % C_;
    int bg = i / C_;
    int b  = bg >> 9;
    int g  = bg & (K_ - 1);
    int j  = rep[b * K_ + g];
    out[CENTER_OFF + i] = pc[((size_t)b * N_ + j) * C_ + c];
}

// ---------------------------------------------------------------------------
// Kernel 3: brute-force kNN (k=32) per center + neighborhood gather.
// One CTA of 256 threads per (batch, center). Distances in transposed
// smem tile sd[i][t] (bank-conflict-free); selection = 32 rounds of
// hierarchical argmin with single-segment rescan.
// Distance matches the reference's expanded form with GEMM-style FMA
// accumulation for the einsum dot: (qq - 2*fma_dot) + tt.
// ---------------------------------------------------------------------------
__global__ __launch_bounds__(256, 1)
void knn_kernel(const float* __restrict__ pc, float* __restrict__ out)
{
    const int blk = blockIdx.x;          // b*K_ + g
    const int b   = blk >> 9;
    const int t   = threadIdx.x;
    const float* base = pc + (size_t)b * N_ * C_;

    __shared__ float sd[GS_ * 256];      // 32 KB, [i][t] layout
    __shared__ float s_wv[8];
    __shared__ int   s_wi[8];
    __shared__ int   s_sel[GS_];
    __shared__ float s_q[3];

    if (t == 0) {
        const float* cen = out + CENTER_OFF + (size_t)blk * C_;
        s_q[0] = cen[0]; s_q[1] = cen[1]; s_q[2] = cen[2];
    }
    __syncthreads();

    const float qx = s_q[0], qy = s_q[1], qz = s_q[2];
    // qq / tt come from elementwise square + reduce (no FMA contraction)
    const float qq = __fadd_rn(__fadd_rn(__fmul_rn(qx, qx), __fmul_rn(qy, qy)),
                               __fmul_rn(qz, qz));

    float bv = FLTMAX;
    int   bi = 0x7fffffff;
#pragma unroll 4
    for (int i = 0; i < GS_; i++) {
        int j = i * 256 + t;
        const float* p = base + (size_t)j * C_;
        float px = p[0], py = p[1], pz = p[2];
        float tt  = __fadd_rn(__fadd_rn(__fmul_rn(px, px), __fmul_rn(py, py)),
                              __fmul_rn(pz, pz));
        // GEMM accumulation: acc = fma(q2,t2, fma(q1,t1, rn(q0*t0)))
        float dot = __fmaf_rn(qz, pz, __fmaf_rn(qy, py, __fmul_rn(qx, px)));
        float d2  = __fadd_rn(__fsub_rn(qq, __fmul_rn(2.0f, dot)), tt);
        sd[i * 256 + t] = d2;
        if (d2 < bv) { bv = d2; bi = j; }   // ascending j -> first-index ties
    }
    __syncthreads();

    for (int r = 0; r < GS_; r++) {
        float v  = bv;
        int   vi = bi;
#pragma unroll
        for (int off = 16; off > 0; off >>= 1) {
            float ov = __shfl_down_sync(0xffffffffu, v, off);
            int   oi = __shfl_down_sync(0xffffffffu, vi, off);
            if (ov < v || (ov == v && oi < vi)) { v = ov; vi = oi; }
        }
        if ((t & 31) == 0) { s_wv[t >> 5] = v; s_wi[t >> 5] = vi; }
        __syncthreads();

        if (t == 0) {
            float mv = s_wv[0]; int mi = s_wi[0];
#pragma unroll
            for (int w = 1; w < 8; w++) {
                float wv = s_wv[w]; int wi = s_wi[w];
                if (wv < mv || (wv == mv && wi < mi)) { mv = wv; mi = wi; }
            }
            s_sel[r] = mi;
        }
        __syncthreads();

        const int win = s_sel[r];
        if (t == (win & 255)) {
            sd[(win >> 8) * 256 + t] = FLTMAX;
            bv = FLTMAX; bi = 0x7fffffff;
#pragma unroll
            for (int i = 0; i < GS_; i++) {
                float v2 = sd[i * 256 + t];
                if (v2 < bv) { bv = v2; bi = i * 256 + t; }
            }
        }
        // next round's reduce is warp-synchronous; s_wv reuse guarded by the
        // barrier after thread 0's read above.
    }
    __syncthreads();

    if (t < GS_) {
        int j = s_sel[t];
        const float* p = base + (size_t)j * C_;
        float* o = out + ((size_t)blk * GS_ + t) * C_;
        o[0] = __fsub_rn(p[0], qx);
        o[1] = __fsub_rn(p[1], qy);
        o[2] = __fsub_rn(p[2], qz);
        o[3] = p[3];
        o[4] = p[4];
        o[5] = p[5];
        out[NN_OFF + (size_t)blk * GS_ + t] = (float)j;
    }
}

// ---------------------------------------------------------------------------
extern "C" void kernel_launch(void* const* d_in, const int* in_sizes, int n_in,
                              void* d_out, int out_size)
{
    const float* pc = (const float*)d_in[0];
    float* out = (float*)d_out;

    int* rep = nullptr;
    cudaGetSymbolAddress((void**)&rep, g_rep);

    fps_kernel<<<B_, 1024>>>(pc, rep);
    center_kernel<<<(CENTER_ELEMS + 255) / 256, 256>>>(pc, rep, out);
    knn_kernel<<<B_ * K_, 256>>>(pc, out);
}

// round 4
// speedup vs baseline: 1.9540x; 1.9540x over previous
#include <cuda_runtime.h>
#include <cuda_bf16.h>
#include <cstdint>

// Problem constants
#define B_      16
#define N_      8192
#define C_      6
#define K_      512      // NUM_GROUP
#define GS_     32       // GROUP_SIZE
#define BIGF    10000000000.0f

// Output layout (float32, concatenated): neighborhood | center | nn_idx
#define NEIGH_ELEMS   (B_*K_*GS_*C_)   // 1,572,864
#define CENTER_ELEMS  (B_*K_*C_)       // 49,152
#define CENTER_OFF    (NEIGH_ELEMS)
#define NN_OFF        (NEIGH_ELEMS + CENTER_ELEMS)

typedef unsigned long long ull;

// Scratch (device globals; no allocation allowed)
__device__ int g_rep[B_ * K_];
__device__ __align__(16) float g_x[B_ * N_];
__device__ __align__(16) float g_y[B_ * N_];
__device__ __align__(16) float g_z[B_ * N_];

// Packed f32x2 ops (Blackwell sm_100+). Per-lane ops are exact rn fp32.
#define ADD2(o,a,b) asm("add.rn.f32x2 %0, %1, %2;" : "=l"(o) : "l"(a), "l"(b))
#define MUL2(o,a,b) asm("mul.rn.f32x2 %0, %1, %2;" : "=l"(o) : "l"(a), "l"(b))

__device__ __forceinline__ ull pk2(float lo, float hi) {
    return (ull)__float_as_uint(lo) | ((ull)__float_as_uint(hi) << 32);
}
__device__ __forceinline__ float plo(ull v) { return __uint_as_float((unsigned)v); }
__device__ __forceinline__ float phi(ull v) { return __uint_as_float((unsigned)(v >> 32)); }

// ---------------------------------------------------------------------------
// Kernel 0: AoS (stride 6) -> SoA xyz transpose.
// ---------------------------------------------------------------------------
__global__ void prep_kernel(const float* __restrict__ pc)
{
    int j = blockIdx.x * 256 + threadIdx.x;
    if (j >= B_ * N_) return;
    const float* p = pc + (size_t)j * C_;
    g_x[j] = p[0]; g_y[j] = p[1]; g_z[j] = p[2];
}

// ---------------------------------------------------------------------------
// Kernel 1: Farthest Point Sampling. One CTA/batch, 512 threads, 16 pts/thread
// in registers (f32x2 packed pairs). Reference numerics: d = ((dx^2+dy^2)+dz^2)
// with rn sub/mul/add (x + (-q) == x - q exactly); dists=min; argmax first-index.
// Reduction: redux(max bits) then redux(min idx); 2 barriers; all warps
// redundantly compute the block winner (no serial warp-0 section).
// Distances are sums of squares >= +0, so u32 bit compare == float compare.
// ---------------------------------------------------------------------------
__global__ __launch_bounds__(512, 1)
void fps_kernel(int* __restrict__ rep)
{
    const int b = blockIdx.x, t = threadIdx.x;
    const int lane = t & 31, w = t >> 5;
    const int base = b * N_;

    float xs[16], ys[16], zs[16];
#pragma unroll
    for (int i = 0; i < 16; i++) {
        int j = base + t + i * 512;
        xs[i] = g_x[j]; ys[i] = g_y[j]; zs[i] = g_z[j];
    }
    ull xp[8], yp[8], zp[8];
#pragma unroll
    for (int p = 0; p < 8; p++) {
        xp[p] = pk2(xs[2*p], xs[2*p+1]);
        yp[p] = pk2(ys[2*p], ys[2*p+1]);
        zp[p] = pk2(zs[2*p], zs[2*p+1]);
    }
    float dst[16];
#pragma unroll
    for (int i = 0; i < 16; i++) dst[i] = BIGF;

    __shared__ float    sq[3];
    __shared__ unsigned sval[16];
    __shared__ unsigned sidx[16];

    float qx = g_x[base], qy = g_y[base], qz = g_z[base];
    int cur = 0;
    int* repb = rep + b * K_;

    for (int k = 0; k < K_; k++) {
        if (t == 0) repb[k] = cur;

        const ull nqx = pk2(-qx, -qx), nqy = pk2(-qy, -qy), nqz = pk2(-qz, -qz);
        float bv = -1.0f; int bi = 0;
#pragma unroll
        for (int p = 0; p < 8; p++) {
            ull dx, dy, dz, s;
            ADD2(dx, xp[p], nqx);
            ADD2(dy, yp[p], nqy);
            ADD2(dz, zp[p], nqz);
            MUL2(dx, dx, dx);
            MUL2(dy, dy, dy);
            MUL2(dz, dz, dz);
            ADD2(s, dx, dy);
            ADD2(s, s, dz);
            float d0 = plo(s), d1 = phi(s);
            float n0 = fminf(dst[2*p],   d0); dst[2*p]   = n0;
            if (n0 > bv) { bv = n0; bi = t + (2*p)   * 512; }
            float n1 = fminf(dst[2*p+1], d1); dst[2*p+1] = n1;
            if (n1 > bv) { bv = n1; bi = t + (2*p+1) * 512; }
        }

        // warp argmax: max bits, then min idx among maxima (exact first-index)
        unsigned mybits = __float_as_uint(bv);
        unsigned mh = __reduce_max_sync(0xffffffffu, mybits);
        unsigned cnd = (mybits == mh) ? (unsigned)bi : 0x7fffffffu;
        unsigned mi = __reduce_min_sync(0xffffffffu, cnd);
        if (lane == 0) { sval[w] = mh; sidx[w] = mi; }
        __syncthreads();

        // every warp computes the block winner (redundant, no 2nd serial stage)
        unsigned v  = (lane < 16) ? sval[lane] : 0u;
        unsigned i2 = (lane < 16) ? sidx[lane] : 0x7fffffffu;
        unsigned Mh = __reduce_max_sync(0xffffffffu, v);
        unsigned c2 = (v == Mh) ? i2 : 0x7fffffffu;
        unsigned Mi = __reduce_min_sync(0xffffffffu, c2);
        cur = (int)Mi;

        if (t == (int)(Mi & 511u)) {
            int i = (int)(Mi >> 9);
            int p = i >> 1;
            if (i & 1) { sq[0] = phi(xp[p]); sq[1] = phi(yp[p]); sq[2] = phi(zp[p]); }
            else       { sq[0] = plo(xp[p]); sq[1] = plo(yp[p]); sq[2] = plo(zp[p]); }
        }
        __syncthreads();
        qx = sq[0]; qy = sq[1]; qz = sq[2];
    }
}

// ---------------------------------------------------------------------------
// Kernel 2: gather centers (all 6 channels) into the output.
// ---------------------------------------------------------------------------
__global__ void center_kernel(const float* __restrict__ pc,
                              const int* __restrict__ rep,
                              float* __restrict__ out)
{
    int i = blockIdx.x * blockDim.x + threadIdx.x;
    if (i >= CENTER_ELEMS) return;
    int c  = i % C_;
    int bg = i / C_;
    int b  = bg >> 9;
    int g  = bg & (K_ - 1);
    int j  = rep[b * K_ + g];
    out[CENTER_OFF + i] = pc[((size_t)b * N_ + j) * C_ + c];
}

// ---------------------------------------------------------------------------
// kNN key: lexicographic u64 (monotone-float-bits(d2) << 32) | idx.
// Matches lax.top_k(-d2) exact order incl. first-index ties. d2 can be
// slightly negative (cancellation) -> monotone transform on bits.
// Distance arithmetic identical to R2-passing kernel: tt rn-chain,
// dot = fma(qz,pz, fma(qy,py, rn(qx*px))), d2 = (qq - 2*dot) + tt.
// ---------------------------------------------------------------------------
__device__ __forceinline__ ull dist_key(float px, float py, float pz, float tt,
                                        float qx, float qy, float qz, float qq, int j)
{
    float dot = __fmaf_rn(qz, pz, __fmaf_rn(qy, py, __fmul_rn(qx, px)));
    float d2  = __fadd_rn(__fsub_rn(qq, __fmul_rn(2.0f, dot)), tt);
    int bb = __float_as_int(d2);
    unsigned u = (unsigned)bb ^ ((unsigned)(bb >> 31) | 0x80000000u);
    return ((ull)u << 32) | (unsigned)j;
}

// ---------------------------------------------------------------------------
// Kernel 3: kNN for 8 centers per CTA (256 thr). Points staged through smem
// in 1024-pt chunks (tt shared across centers). Each thread keeps top-2 u64
// keys per center. Then warp w extracts top-32 for center w from the 512
// candidates with redux-min rounds; when a thread's both candidates are
// consumed, exact refill = min{key > last_extracted} rescanned from gmem.
// ---------------------------------------------------------------------------
#define GC     8
#define CHUNK  1024

__global__ __launch_bounds__(256, 1)
void knn_kernel(const float* __restrict__ pc, float* __restrict__ out)
{
    __shared__ __align__(16) float scx[CHUNK];
    __shared__ __align__(16) float scy[CHUNK];
    __shared__ __align__(16) float scz[CHUNK];
    __shared__ ull   cands[GC][256][2];
    __shared__ float scq[GC][3];
    __shared__ float sqq[GC];

    const int t = threadIdx.x, lane = t & 31, w = t >> 5;
    const int blk = blockIdx.x;
    const int b = blk >> 6;                 // 64 CTAs per batch (512/8)
    const int cen0 = (blk & 63) * GC;
    const int bbase = b * N_;

    if (t < GC) {
        int gcen = b * K_ + cen0 + t;
        const float* cp = out + CENTER_OFF + (size_t)gcen * C_;
        float qx = cp[0], qy = cp[1], qz = cp[2];
        scq[t][0] = qx; scq[t][1] = qy; scq[t][2] = qz;
        sqq[t] = __fadd_rn(__fadd_rn(__fmul_rn(qx, qx), __fmul_rn(qy, qy)),
                           __fmul_rn(qz, qz));
    }

    ull c0[GC], c1[GC];
#pragma unroll
    for (int c = 0; c < GC; c++) { c0[c] = ~0ull; c1[c] = ~0ull; }
    __syncthreads();

    for (int ch = 0; ch < N_ / CHUNK; ch++) {
        ((float4*)scx)[t] = ((const float4*)(g_x + bbase + ch * CHUNK))[t];
        ((float4*)scy)[t] = ((const float4*)(g_y + bbase + ch * CHUNK))[t];
        ((float4*)scz)[t] = ((const float4*)(g_z + bbase + ch * CHUNK))[t];
        __syncthreads();
#pragma unroll
        for (int l = 0; l < CHUNK / 256; l++) {
            int jj = l * 256 + t;
            int j  = ch * CHUNK + jj;
            float px = scx[jj], py = scy[jj], pz = scz[jj];
            float tt = __fadd_rn(__fadd_rn(__fmul_rn(px, px), __fmul_rn(py, py)),
                                 __fmul_rn(pz, pz));
#pragma unroll
            for (int c = 0; c < GC; c++) {
                ull key = dist_key(px, py, pz, tt,
                                   scq[c][0], scq[c][1], scq[c][2], sqq[c], j);
                if (key < c1[c]) {
                    if (key < c0[c]) { c1[c] = c0[c]; c0[c] = key; }
                    else             { c1[c] = key; }
                }
            }
        }
        __syncthreads();
    }

#pragma unroll
    for (int c = 0; c < GC; c++) { cands[c][t][0] = c0[c]; cands[c][t][1] = c1[c]; }
    __syncthreads();

    // ---- selection: warp w -> center w; lane owns threads lane*8 + o ----
    const float qx = scq[w][0], qy = scq[w][1], qz = scq[w][2], qq = sqq[w];

    ull fr[8]; int st[8];
#pragma unroll
    for (int o = 0; o < 8; o++) { fr[o] = cands[w][lane * 8 + o][0]; st[o] = 0; }
    ull lm = fr[0]; int ow = 0;
#pragma unroll
    for (int o = 1; o < 8; o++) if (fr[o] < lm) { lm = fr[o]; ow = o; }

    int selidx = 0;
    for (int r = 0; r < GS_; r++) {
        unsigned hi  = (unsigned)(lm >> 32);
        unsigned mh  = __reduce_min_sync(0xffffffffu, hi);
        unsigned cnd = (hi == mh) ? (unsigned)lm : 0xffffffffu;
        unsigned mi  = __reduce_min_sync(0xffffffffu, cnd);
        if (lane == r) selidx = (int)mi;

        if (hi == mh && (unsigned)lm == mi) {         // this lane owned the winner
            int o = ow, T = lane * 8 + o;
            if (st[o] == 0) { fr[o] = cands[w][T][1]; st[o] = 1; }
            else {
                // exact refill: min key strictly greater than last extracted
                ull best = ~0ull;
                const ull th = lm;
                for (int i = 0; i < 32; i++) {
                    int j2 = i * 256 + T;
                    float px = g_x[bbase + j2], py = g_y[bbase + j2], pz = g_z[bbase + j2];
                    float tt = __fadd_rn(__fadd_rn(__fmul_rn(px, px), __fmul_rn(py, py)),
                                         __fmul_rn(pz, pz));
                    ull key = dist_key(px, py, pz, tt, qx, qy, qz, qq, j2);
                    if (key > th && key < best) best = key;
                }
                fr[o] = best;
            }
            lm = fr[0]; ow = 0;
#pragma unroll
            for (int o2 = 1; o2 < 8; o2++) if (fr[o2] < lm) { lm = fr[o2]; ow = o2; }
        }
    }

    // ---- output: lane L holds rank-L neighbor for center w ----
    const int gcen = b * K_ + cen0 + w;
    const int j = selidx;
    float px = g_x[bbase + j], py = g_y[bbase + j], pz = g_z[bbase + j];
    const float* pf = pc + ((size_t)(bbase + j)) * C_;
    float* o6 = out + ((size_t)gcen * GS_ + lane) * C_;
    o6[0] = __fsub_rn(px, qx);
    o6[1] = __fsub_rn(py, qy);
    o6[2] = __fsub_rn(pz, qz);
    o6[3] = pf[3];
    o6[4] = pf[4];
    o6[5] = pf[5];
    out[NN_OFF + (size_t)gcen * GS_ + lane] = (float)j;
}

// ---------------------------------------------------------------------------
extern "C" void kernel_launch(void* const* d_in, const int* in_sizes, int n_in,
                              void* d_out, int out_size)
{
    const float* pc = (const float*)d_in[0];
    float* out = (float*)d_out;

    int* rep = nullptr;
    cudaGetSymbolAddress((void**)&rep, g_rep);

    prep_kernel<<<(B_ * N_ + 255) / 256, 256>>>(pc);
    fps_kernel<<<B_, 512>>>(rep);
    center_kernel<<<(CENTER_ELEMS + 255) / 256, 256>>>(pc, rep, out);
    knn_kernel<<<B_ * K_ / GC, 256>>>(pc, out);
}